// round 14
// baseline (speedup 1.0000x reference)
#include <cuda_runtime.h>
#include <cuda_bf16.h>

typedef unsigned int uint32;
typedef unsigned short u16;

// ---------------- problem constants ----------------
constexpr int N_EL  = 300000;
constexpr int SENS  = 64;
constexpr int TICKS = 1024;
constexpr int HID   = 128;

// ---------------- global scratch ----------------
constexpr int NBIN = 32;       // 32-tick tiles
constexpr int BCAP = 16384;
constexpr int WV_R = 5;        // gaussian inclusion radius (ticks)

__device__ uint32 g_Rbin[(size_t)NBIN * BCAP * 32];  // bin-ordered response bf16x2 (64 MB)
__device__ float  g_binZ[NBIN * BCAP];
__device__ int    g_binCnt[NBIN];
__device__ int    g_done[NBIN];
__device__ int2   g_perm[N_EL];                      // per-electron bin slots (x, y; -1 = none)

// ---------------- helpers ----------------
__device__ __forceinline__ void mma16816(float* c, uint32 a0, uint32 a1, uint32 a2, uint32 a3,
                                         uint32 b0, uint32 b1) {
    asm volatile(
        "mma.sync.aligned.m16n8k16.row.col.f32.bf16.bf16.f32 "
        "{%0,%1,%2,%3},{%4,%5,%6,%7},{%8,%9},{%0,%1,%2,%3};\n"
        : "+f"(c[0]), "+f"(c[1]), "+f"(c[2]), "+f"(c[3])
        : "r"(a0), "r"(a1), "r"(a2), "r"(a3), "r"(b0), "r"(b1));
}

__device__ __forceinline__ void ldsm4(uint32& r0, uint32& r1, uint32& r2, uint32& r3,
                                      uint32 addr) {
    asm volatile("ldmatrix.sync.aligned.m8n8.x4.shared.b16 {%0,%1,%2,%3}, [%4];"
        : "=r"(r0), "=r"(r1), "=r"(r2), "=r"(r3) : "r"(addr));
}

__device__ __forceinline__ void ldsm4t(uint32& r0, uint32& r1, uint32& r2, uint32& r3,
                                       uint32 addr) {
    asm volatile("ldmatrix.sync.aligned.m8n8.x4.trans.shared.b16 {%0,%1,%2,%3}, [%4];"
        : "=r"(r0), "=r"(r1), "=r"(r2), "=r"(r3) : "r"(addr));
}

__device__ __forceinline__ uint32 smem_u32(const void* p) {
    uint32 a;
    asm("{ .reg .u64 t; cvta.to.shared.u64 t, %1; cvt.u32.u64 %0, t; }" : "=r"(a) : "l"(p));
    return a;
}

__device__ __forceinline__ uint32 packbf2(float a, float b) {
    __nv_bfloat162 t = __floats2bfloat162_rn(a, b);
    return *reinterpret_cast<uint32*>(&t);
}

// MUFU-based sigmoid: EX2 + RCP (~5 issues)
__device__ __forceinline__ float sigmoid_mufu(float x) {
    return __fdividef(1.f, 1.f + __expf(-x));
}

// ======================= MLP kernel (GEMM1 via FFMA; GEMM2/3 as R12) ====================
constexpr int KP  = 136;
constexpr int NWT = N_EL / 16;       // 18750
constexpr int MLP_GRID = 296;

constexpr int OFF_W2T = 0;                          // [128][KP] bf16 = 34816 B
constexpr int OFF_W3T = OFF_W2T + HID * KP * 2;     // [64][KP]  bf16 = 17408 B
constexpr int OFF_W1  = OFF_W3T + SENS * KP * 2;    // float[256]
constexpr int OFF_B1  = OFF_W1 + 256 * 4;           // float[128]
constexpr int OFF_B2  = OFF_B1 + 128 * 4;           // float[128]
constexpr int OFF_B3  = OFF_B2 + 128 * 4;           // float[64]
constexpr int MLP_SMEM = OFF_B3 + 64 * 4;           // ~55 KB

__global__ __launch_bounds__(256, 2)
void mlp_kernel(const float* __restrict__ photons,
                const float2* __restrict__ xy,
                const float* __restrict__ W1, const float* __restrict__ b1,
                const float* __restrict__ W2, const float* __restrict__ b2,
                const float* __restrict__ W3, const float* __restrict__ b3) {
    extern __shared__ unsigned char sm[];
    __nv_bfloat16* sW2t = reinterpret_cast<__nv_bfloat16*>(sm + OFF_W2T);
    __nv_bfloat16* sW3t = reinterpret_cast<__nv_bfloat16*>(sm + OFF_W3T);
    float* sW1 = reinterpret_cast<float*>(sm + OFF_W1);
    float* sB1 = reinterpret_cast<float*>(sm + OFF_B1);
    float* sB2 = reinterpret_cast<float*>(sm + OFF_B2);
    float* sB3 = reinterpret_cast<float*>(sm + OFF_B3);

    const int tid = threadIdx.x;
    for (int i = tid; i < HID * HID; i += 256) {
        int k = i >> 7, n = i & 127;
        sW2t[n * KP + k] = __float2bfloat16_rn(W2[i]);
    }
    for (int i = tid; i < HID * SENS; i += 256) {
        int k = i >> 6, n = i & 63;
        sW3t[n * KP + k] = __float2bfloat16_rn(W3[i]);
    }
    for (int i = tid; i < 256; i += 256) sW1[i] = W1[i];
    if (tid < 128) { sB1[tid] = b1[tid]; sB2[tid] = b2[tid]; }
    if (tid < 64)  sB3[tid] = b3[tid];
    __syncthreads();

    const int wid = tid >> 5, lane = tid & 31;
    const int g = lane >> 2, tg = lane & 3;
    const int kq = tg * 2;

    const int row_in = (lane & 7) + ((lane >> 4) << 3);
    const int k8off  = (lane >> 3) & 1;
    const uint32 lmB2 = smem_u32(sW2t) + (uint32)(row_in * (KP * 2) + k8off * 16);
    const uint32 lmB3 = smem_u32(sW3t) + (uint32)(row_in * (KP * 2) + k8off * 16);

    const int wslot   = blockIdx.x * 8 + wid;
    const int wstride = gridDim.x * 8;

    for (int wt = wslot; wt < NWT; wt += wstride) {
        const int r0 = wt * 16 + g, r1 = r0 + 8;
        const float2 p0 = xy[r0], p1 = xy[r1];
        const float ph0 = photons[r0], ph1 = photons[r1];
        const int2 pm0 = g_perm[r0];
        const int2 pm1 = g_perm[r1];

        // ---- GEMM1 via FFMA: h1 = relu(xy@W1 + b1) -> A2 fragments (R3-proven) ----
        uint32 A2[32];
        #pragma unroll
        for (int kt = 0; kt < 8; kt++) {
            const int kc = kt * 16 + kq;
            float w1a0 = sW1[kc],     w1b0 = sW1[128 + kc];
            float w1a1 = sW1[kc + 1], w1b1 = sW1[128 + kc + 1];
            float w1a2 = sW1[kc + 8], w1b2 = sW1[128 + kc + 8];
            float w1a3 = sW1[kc + 9], w1b3 = sW1[128 + kc + 9];
            float bb0 = sB1[kc], bb1 = sB1[kc + 1], bb2 = sB1[kc + 8], bb3 = sB1[kc + 9];
            float h00 = fmaxf(fmaf(p0.y, w1b0, fmaf(p0.x, w1a0, bb0)), 0.f);
            float h01 = fmaxf(fmaf(p0.y, w1b1, fmaf(p0.x, w1a1, bb1)), 0.f);
            float h10 = fmaxf(fmaf(p1.y, w1b0, fmaf(p1.x, w1a0, bb0)), 0.f);
            float h11 = fmaxf(fmaf(p1.y, w1b1, fmaf(p1.x, w1a1, bb1)), 0.f);
            float h02 = fmaxf(fmaf(p0.y, w1b2, fmaf(p0.x, w1a2, bb2)), 0.f);
            float h03 = fmaxf(fmaf(p0.y, w1b3, fmaf(p0.x, w1a3, bb3)), 0.f);
            float h12 = fmaxf(fmaf(p1.y, w1b2, fmaf(p1.x, w1a2, bb2)), 0.f);
            float h13 = fmaxf(fmaf(p1.y, w1b3, fmaf(p1.x, w1a3, bb3)), 0.f);
            A2[kt * 4 + 0] = packbf2(h00, h01);
            A2[kt * 4 + 1] = packbf2(h10, h11);
            A2[kt * 4 + 2] = packbf2(h02, h03);
            A2[kt * 4 + 3] = packbf2(h12, h13);
        }

        float acc2[64];
        #pragma unroll
        for (int i = 0; i < 64; i++) acc2[i] = 0.f;
        #pragma unroll
        for (int kt = 0; kt < 8; kt++) {
            #pragma unroll
            for (int p = 0; p < 8; p++) {
                uint32 b0, b1r, b2r, b3r;
                ldsm4(b0, b1r, b2r, b3r, lmB2 + (uint32)(p * 16 * (KP * 2) + kt * 32));
                mma16816(&acc2[(2 * p) * 4], A2[kt * 4 + 0], A2[kt * 4 + 1],
                         A2[kt * 4 + 2], A2[kt * 4 + 3], b0, b1r);
                mma16816(&acc2[(2 * p + 1) * 4], A2[kt * 4 + 0], A2[kt * 4 + 1],
                         A2[kt * 4 + 2], A2[kt * 4 + 3], b2r, b3r);
            }
        }

        uint32 A3[32];
        #pragma unroll
        for (int kt = 0; kt < 8; kt++) {
            const int nt0 = 2 * kt, nt1 = nt0 + 1;
            const int c0 = nt0 * 8 + kq, c1 = nt1 * 8 + kq;
            float b20 = sB2[c0], b21 = sB2[c0 + 1];
            float b22 = sB2[c1], b23 = sB2[c1 + 1];
            A3[kt * 4 + 0] = packbf2(fmaxf(acc2[nt0 * 4 + 0] + b20, 0.f),
                                     fmaxf(acc2[nt0 * 4 + 1] + b21, 0.f));
            A3[kt * 4 + 1] = packbf2(fmaxf(acc2[nt0 * 4 + 2] + b20, 0.f),
                                     fmaxf(acc2[nt0 * 4 + 3] + b21, 0.f));
            A3[kt * 4 + 2] = packbf2(fmaxf(acc2[nt1 * 4 + 0] + b22, 0.f),
                                     fmaxf(acc2[nt1 * 4 + 1] + b23, 0.f));
            A3[kt * 4 + 3] = packbf2(fmaxf(acc2[nt1 * 4 + 2] + b22, 0.f),
                                     fmaxf(acc2[nt1 * 4 + 3] + b23, 0.f));
        }

        float acc3[32];
        #pragma unroll
        for (int i = 0; i < 32; i++) acc3[i] = 0.f;
        #pragma unroll
        for (int kt = 0; kt < 8; kt++) {
            #pragma unroll
            for (int p = 0; p < 4; p++) {
                uint32 b0, b1r, b2r, b3r;
                ldsm4(b0, b1r, b2r, b3r, lmB3 + (uint32)(p * 16 * (KP * 2) + kt * 32));
                mma16816(&acc3[(2 * p) * 4], A3[kt * 4 + 0], A3[kt * 4 + 1],
                         A3[kt * 4 + 2], A3[kt * 4 + 3], b0, b1r);
                mma16816(&acc3[(2 * p + 1) * 4], A3[kt * 4 + 0], A3[kt * 4 + 1],
                         A3[kt * 4 + 2], A3[kt * 4 + 3], b2r, b3r);
            }
        }

        // ---- epilogue: scatter r = photons*sigmoid(acc3+b3) to bin-ordered rows ----
        #pragma unroll
        for (int nt = 0; nt < 8; nt++) {
            const int c0 = nt * 8 + kq;
            float bb0 = sB3[c0], bb1 = sB3[c0 + 1];
            float s0 = sigmoid_mufu(acc3[nt * 4 + 0] + bb0);
            float s1 = sigmoid_mufu(acc3[nt * 4 + 1] + bb1);
            float s2 = sigmoid_mufu(acc3[nt * 4 + 2] + bb0);
            float s3 = sigmoid_mufu(acc3[nt * 4 + 3] + bb1);
            const uint32 w0 = packbf2(ph0 * s0, ph0 * s1);
            const uint32 w1 = packbf2(ph1 * s2, ph1 * s3);
            const int col = nt * 4 + tg;
            if (pm0.x >= 0) g_Rbin[(size_t)pm0.x * 32 + col] = w0;
            if (pm0.y >= 0) g_Rbin[(size_t)pm0.y * 32 + col] = w0;
            if (pm1.x >= 0) g_Rbin[(size_t)pm1.x * 32 + col] = w1;
            if (pm1.y >= 0) g_Rbin[(size_t)pm1.y * 32 + col] = w1;
        }
    }
}

// ---------------- binning kernel (R12 passing version, verbatim) ----------------
constexpr int BIN_BLOCKS = (N_EL / 4 + 255) / 256;   // 293

__global__ __launch_bounds__(256)
void bin_kernel(const float4* __restrict__ zpos4, float4* __restrict__ out4) {
    __shared__ int hist[NBIN], sbase[NBIN];
    const int tid = threadIdx.x;
    if (tid < NBIN) hist[tid] = 0;

    if (blockIdx.x < 64) out4[blockIdx.x * 256 + tid] = make_float4(0.f, 0.f, 0.f, 0.f);
    __syncthreads();

    const int t4 = blockIdx.x * 256 + tid;
    float zv[4];
    int tlo[4], thi[4], slo[4], shi[4];
    bool valid = (t4 < N_EL / 4);
    if (valid) {
        float4 z4 = zpos4[t4];
        zv[0] = z4.x; zv[1] = z4.y; zv[2] = z4.z; zv[3] = z4.w;
        #pragma unroll
        for (int q = 0; q < 4; q++) {
            int c = __float2int_rn(zv[q]);
            int lo = max(c - WV_R, 0) >> 5;
            int hi = min(c + WV_R, TICKS - 1) >> 5;
            tlo[q] = lo; slo[q] = atomicAdd(&hist[lo], 1);
            if (hi != lo) { thi[q] = hi; shi[q] = atomicAdd(&hist[hi], 1); }
            else thi[q] = -1;
        }
    }
    __syncthreads();
    if (tid < NBIN) sbase[tid] = atomicAdd(&g_binCnt[tid], hist[tid]);
    __syncthreads();
    if (valid) {
        #pragma unroll
        for (int q = 0; q < 4; q++) {
            const int idx = t4 * 4 + q;
            int e0 = -1, e1 = -1;
            int p = sbase[tlo[q]] + slo[q];
            if (p < BCAP) { g_binZ[tlo[q] * BCAP + p] = zv[q]; e0 = tlo[q] * BCAP + p; }
            if (thi[q] >= 0) {
                int p2 = sbase[thi[q]] + shi[q];
                if (p2 < BCAP) { g_binZ[thi[q] * BCAP + p2] = zv[q]; e1 = thi[q] * BCAP + p2; }
            }
            g_perm[idx] = make_int2(e0, e1);
        }
    }
}

// ======================= waveform kernel (R12 version + tail binCnt reset) ==============
constexpr int WV_NSL = 24;
constexpr float CNORM = 0.3989422804f;

constexpr int EST_S = 264;   // u16 row stride (528 B, aligned + conflict-free)
constexpr int RS2_S = 72;    // u16 row stride (144 B, aligned)
constexpr int WOFF_EST = 0;                          // u16[32*264]  = 16896 B
constexpr int WOFF_RS2 = WOFF_EST + 32 * EST_S * 2;  // u16[256*72]  = 36864 B
constexpr int WV_SMEM  = WOFF_RS2 + 256 * RS2_S * 2; // ~52.5 KB

__global__ __launch_bounds__(256, 2)
void waveform_gemm(float* __restrict__ out) {
    extern __shared__ unsigned char sm[];
    u16*    EST  = reinterpret_cast<u16*>(sm + WOFF_EST);
    uint32* RS2w = reinterpret_cast<uint32*>(sm + WOFF_RS2);

    const int tid  = threadIdx.x;
    const int lane = tid & 31;
    const int wid  = tid >> 5;
    const int g    = lane >> 2, tg = lane & 3;
    const int tile = blockIdx.x;
    const int t0   = tile * 32;

    const int cnt = min(g_binCnt[tile], BCAP);
    const int nc  = (cnt + 255) >> 8;       // whole chunks
    const int emax = cnt - 1;

    float C[8];
    #pragma unroll
    for (int i = 0; i < 8; i++) C[i] = 0.f;

    const int mt = wid & 3;       // m-tile (16 sensors)
    const int nh = wid >> 2;      // n-half (16 ticks)

    const int arow = (lane & 7) + ((lane >> 4) << 3);
    const int acol = mt * 16 + ((lane >> 3) & 1) * 8;
    const uint32 lmA = smem_u32(sm + WOFF_RS2) + (uint32)((arow * RS2_S + acol) * 2);
    const int rowB = (lane & 7) + ((lane >> 4) << 3);
    const uint32 lmB = smem_u32(sm + WOFF_EST) +
        (uint32)(((nh * 16 + rowB) * EST_S + (((lane >> 3) & 1) * 8)) * 2);

    for (int c = blockIdx.y; c < nc; c += WV_NSL) {
        const int cb = c << 8;
        const int cend = min(cb + 256, cnt);

        // ---- build E^T: direct gaussian eval, 32 independent EX2s ----
        {
            const int e = cb + tid;
            const float zz = g_binZ[tile * BCAP + min(e, emax)];
            const float cn = (e < cend) ? CNORM : 0.f;
            const float d0 = (float)t0 - zz;
            #pragma unroll
            for (int j = 0; j < 32; j++) {
                float d = d0 + (float)j;
                float ex = __expf(-0.5f * d * d);
                EST[j * EST_S + tid] = __bfloat16_as_ushort(__float2bfloat16_rn(cn * ex));
            }
        }
        // ---- load R rows (sequential, coalesced 128-bit) -> RS2 staging ----
        {
            const uint32* src = g_Rbin + ((size_t)tile * BCAP + cb + wid * 32) * 32;
            const int lrow_in = (lane >> 3);
            const int word = (lane & 7) * 4;
            #pragma unroll
            for (int q = 0; q < 8; q++) {
                const int lrow = q * 4 + lrow_in;   // 0..31 within warp's 32 rows
                uint4 v = *reinterpret_cast<const uint4*>(src + lrow * 32 + word);
                *reinterpret_cast<uint4*>(&RS2w[(wid * 32 + lrow) * (RS2_S / 2) + word]) = v;
            }
        }
        __syncthreads();

        // ---- GEMM: C += R^T @ E over K=256 (A via ldsm.trans, B via ldsm) ----
        #pragma unroll
        for (int ks = 0; ks < 16; ks++) {
            uint32 a0, a1, a2, a3, b0, b1, b2, b3;
            ldsm4t(a0, a1, a2, a3, lmA + (uint32)(ks * 16 * RS2_S * 2));
            ldsm4 (b0, b1, b2, b3, lmB + (uint32)(ks * 32));
            mma16816(&C[0], a0, a1, a2, a3, b0, b1);
            mma16816(&C[4], a0, a1, a2, a3, b2, b3);
        }
        __syncthreads();
    }

    // ---- epilogue: scatter C fragments via atomics ----
    #pragma unroll
    for (int nt = 0; nt < 2; nt++) {
        const int tcol = t0 + (nh * 2 + nt) * 8 + 2 * tg;
        const int srow = mt * 16 + g;
        atomicAdd(&out[srow * 1024 + tcol],           C[nt * 4 + 0]);
        atomicAdd(&out[srow * 1024 + tcol + 1],       C[nt * 4 + 1]);
        atomicAdd(&out[(srow + 8) * 1024 + tcol],     C[nt * 4 + 2]);
        atomicAdd(&out[(srow + 8) * 1024 + tcol + 1], C[nt * 4 + 3]);
    }

    // ---- tail: last y-slice of this tile resets bin counters for the next replay ----
    // Safe: every y-block reads g_binCnt[tile] at entry and increments g_done at exit,
    // so the (WV_NSL)th arrival implies all readers of this launch are done.
    if (tid == 0) {
        int d = atomicAdd(&g_done[tile], 1);
        if (d == WV_NSL - 1) { g_binCnt[tile] = 0; g_done[tile] = 0; }
    }
}

// ---------------- launch ----------------
extern "C" void kernel_launch(void* const* d_in, const int* in_sizes, int n_in,
                              void* d_out, int out_size) {
    const float*  photons = (const float*)d_in[0];
    const float2* xy      = (const float2*)d_in[1];
    const float*  zpos    = (const float*)d_in[2];
    const float*  W1      = (const float*)d_in[3];
    const float*  b1      = (const float*)d_in[4];
    const float*  W2      = (const float*)d_in[5];
    const float*  b2      = (const float*)d_in[6];
    const float*  W3      = (const float*)d_in[7];
    const float*  b3      = (const float*)d_in[8];
    float* out = (float*)d_out;

    cudaFuncSetAttribute(mlp_kernel, cudaFuncAttributeMaxDynamicSharedMemorySize, MLP_SMEM);
    cudaFuncSetAttribute(waveform_gemm, cudaFuncAttributeMaxDynamicSharedMemorySize, WV_SMEM);

    bin_kernel<<<BIN_BLOCKS, 256>>>((const float4*)zpos, (float4*)out);
    mlp_kernel<<<MLP_GRID, 256, MLP_SMEM>>>(photons, xy, W1, b1, W2, b2, W3, b3);

    dim3 wgrid(TICKS / 32, WV_NSL);
    waveform_gemm<<<wgrid, 256, WV_SMEM>>>(out);
}

// round 15
// speedup vs baseline: 1.0537x; 1.0537x over previous
#include <cuda_runtime.h>
#include <cuda_bf16.h>

typedef unsigned int uint32;
typedef unsigned short u16;

// ---------------- problem constants ----------------
constexpr int N_EL  = 300000;
constexpr int SENS  = 64;
constexpr int TICKS = 1024;
constexpr int HID   = 128;

// ---------------- global scratch ----------------
constexpr int NBIN = 32;       // 32-tick tiles
constexpr int BCAP = 16384;
constexpr int WV_R = 5;        // gaussian inclusion radius (ticks)

__device__ uint32 g_Rbin[(size_t)NBIN * BCAP * 32];  // bin-ordered response bf16x2 (64 MB)
__device__ float  g_binZ[NBIN * BCAP];
__device__ int    g_binCnt[NBIN];
__device__ int    g_done[NBIN];
__device__ int2   g_perm[N_EL];                      // per-electron bin slots (x, y; -1 = none)

// ---------------- helpers ----------------
__device__ __forceinline__ void mma16816(float* c, uint32 a0, uint32 a1, uint32 a2, uint32 a3,
                                         uint32 b0, uint32 b1) {
    asm volatile(
        "mma.sync.aligned.m16n8k16.row.col.f32.bf16.bf16.f32 "
        "{%0,%1,%2,%3},{%4,%5,%6,%7},{%8,%9},{%0,%1,%2,%3};\n"
        : "+f"(c[0]), "+f"(c[1]), "+f"(c[2]), "+f"(c[3])
        : "r"(a0), "r"(a1), "r"(a2), "r"(a3), "r"(b0), "r"(b1));
}

__device__ __forceinline__ void ldsm4(uint32& r0, uint32& r1, uint32& r2, uint32& r3,
                                      uint32 addr) {
    asm volatile("ldmatrix.sync.aligned.m8n8.x4.shared.b16 {%0,%1,%2,%3}, [%4];"
        : "=r"(r0), "=r"(r1), "=r"(r2), "=r"(r3) : "r"(addr));
}

__device__ __forceinline__ void ldsm4t(uint32& r0, uint32& r1, uint32& r2, uint32& r3,
                                       uint32 addr) {
    asm volatile("ldmatrix.sync.aligned.m8n8.x4.trans.shared.b16 {%0,%1,%2,%3}, [%4];"
        : "=r"(r0), "=r"(r1), "=r"(r2), "=r"(r3) : "r"(addr));
}

__device__ __forceinline__ uint32 smem_u32(const void* p) {
    uint32 a;
    asm("{ .reg .u64 t; cvta.to.shared.u64 t, %1; cvt.u32.u64 %0, t; }" : "=r"(a) : "l"(p));
    return a;
}

__device__ __forceinline__ uint32 packbf2(float a, float b) {
    __nv_bfloat162 t = __floats2bfloat162_rn(a, b);
    return *reinterpret_cast<uint32*>(&t);
}

// MUFU-based sigmoid: EX2 + RCP (~5 issues)
__device__ __forceinline__ float sigmoid_mufu(float x) {
    return __fdividef(1.f, 1.f + __expf(-x));
}

// ======================= MLP kernel (R12 passing version, verbatim) =====================
constexpr int KP  = 136;
constexpr int NWT = N_EL / 16;       // 18750
constexpr int MLP_GRID = 296;

constexpr int OFF_W2T = 0;                          // [128][KP] bf16 = 34816 B
constexpr int OFF_W3T = OFF_W2T + HID * KP * 2;     // [64][KP]  bf16 = 17408 B
constexpr int OFF_W1E = OFF_W3T + SENS * KP * 2;    // [128][16] bf16 = 4096 B
constexpr int OFF_B2  = OFF_W1E + 128 * 16 * 2;     // float[128]
constexpr int OFF_B3  = OFF_B2 + 128 * 4;           // float[64]
constexpr int MLP_SMEM = OFF_B3 + 64 * 4;           // ~57 KB

__global__ __launch_bounds__(256, 2)
void mlp_kernel(const float* __restrict__ photons,
                const float2* __restrict__ xy,
                const float* __restrict__ W1, const float* __restrict__ b1,
                const float* __restrict__ W2, const float* __restrict__ b2,
                const float* __restrict__ W3, const float* __restrict__ b3) {
    extern __shared__ unsigned char sm[];
    __nv_bfloat16* sW2t = reinterpret_cast<__nv_bfloat16*>(sm + OFF_W2T);
    __nv_bfloat16* sW3t = reinterpret_cast<__nv_bfloat16*>(sm + OFF_W3T);
    __nv_bfloat16* sW1e = reinterpret_cast<__nv_bfloat16*>(sm + OFF_W1E);
    float* sB2 = reinterpret_cast<float*>(sm + OFF_B2);
    float* sB3 = reinterpret_cast<float*>(sm + OFF_B3);

    const int tid = threadIdx.x;
    for (int i = tid; i < HID * HID; i += 256) {
        int k = i >> 7, n = i & 127;
        sW2t[n * KP + k] = __float2bfloat16_rn(W2[i]);
    }
    for (int i = tid; i < HID * SENS; i += 256) {
        int k = i >> 6, n = i & 63;
        sW3t[n * KP + k] = __float2bfloat16_rn(W3[i]);
    }
    for (int i = tid; i < 128 * 16; i += 256) {
        int n = i >> 4, k = i & 15;
        float v = (k == 0) ? W1[n] : (k == 1) ? W1[128 + n] : (k == 2) ? b1[n] : 0.f;
        sW1e[i] = __float2bfloat16_rn(v);
    }
    if (tid < 128) sB2[tid] = b2[tid];
    if (tid < 64)  sB3[tid] = b3[tid];
    __syncthreads();

    const int wid = tid >> 5, lane = tid & 31;
    const int g = lane >> 2, tg = lane & 3;
    const int kq = tg * 2;

    const int row_in = (lane & 7) + ((lane >> 4) << 3);
    const int k8off  = (lane >> 3) & 1;
    const uint32 lmB2 = smem_u32(sW2t) + (uint32)(row_in * (KP * 2) + k8off * 16);
    const uint32 lmB3 = smem_u32(sW3t) + (uint32)(row_in * (KP * 2) + k8off * 16);

    const int wslot   = blockIdx.x * 8 + wid;
    const int wstride = gridDim.x * 8;

    for (int wt = wslot; wt < NWT; wt += wstride) {
        const int r0 = wt * 16 + g, r1 = r0 + 8;
        const float2 p0 = xy[r0], p1 = xy[r1];
        const float ph0 = photons[r0], ph1 = photons[r1];
        const int2 pm0 = g_perm[r0];
        const int2 pm1 = g_perm[r1];

        float acc1[64];
        #pragma unroll
        for (int i = 0; i < 64; i++) acc1[i] = 0.f;
        const uint32 xa0 = (tg == 0) ? packbf2(p0.x, p0.y) : ((tg == 1) ? 0x00003F80u : 0u);
        const uint32 xa1 = (tg == 0) ? packbf2(p1.x, p1.y) : ((tg == 1) ? 0x00003F80u : 0u);
        #pragma unroll
        for (int nt = 0; nt < 16; nt++) {
            uint32 b0 = *reinterpret_cast<const uint32*>(sW1e + (nt * 8 + g) * 16 + kq);
            mma16816(&acc1[nt * 4], xa0, xa1, 0u, 0u, b0, 0u);
        }

        uint32 A2[32];
        #pragma unroll
        for (int kt = 0; kt < 8; kt++) {
            A2[kt * 4 + 0] = packbf2(fmaxf(acc1[8 * kt + 0], 0.f), fmaxf(acc1[8 * kt + 1], 0.f));
            A2[kt * 4 + 1] = packbf2(fmaxf(acc1[8 * kt + 2], 0.f), fmaxf(acc1[8 * kt + 3], 0.f));
            A2[kt * 4 + 2] = packbf2(fmaxf(acc1[8 * kt + 4], 0.f), fmaxf(acc1[8 * kt + 5], 0.f));
            A2[kt * 4 + 3] = packbf2(fmaxf(acc1[8 * kt + 6], 0.f), fmaxf(acc1[8 * kt + 7], 0.f));
        }

        float acc2[64];
        #pragma unroll
        for (int i = 0; i < 64; i++) acc2[i] = 0.f;
        #pragma unroll
        for (int kt = 0; kt < 8; kt++) {
            #pragma unroll
            for (int p = 0; p < 8; p++) {
                uint32 b0, b1r, b2r, b3r;
                ldsm4(b0, b1r, b2r, b3r, lmB2 + (uint32)(p * 16 * (KP * 2) + kt * 32));
                mma16816(&acc2[(2 * p) * 4], A2[kt * 4 + 0], A2[kt * 4 + 1],
                         A2[kt * 4 + 2], A2[kt * 4 + 3], b0, b1r);
                mma16816(&acc2[(2 * p + 1) * 4], A2[kt * 4 + 0], A2[kt * 4 + 1],
                         A2[kt * 4 + 2], A2[kt * 4 + 3], b2r, b3r);
            }
        }

        uint32 A3[32];
        #pragma unroll
        for (int kt = 0; kt < 8; kt++) {
            const int nt0 = 2 * kt, nt1 = nt0 + 1;
            const int c0 = nt0 * 8 + kq, c1 = nt1 * 8 + kq;
            float b20 = sB2[c0], b21 = sB2[c0 + 1];
            float b22 = sB2[c1], b23 = sB2[c1 + 1];
            A3[kt * 4 + 0] = packbf2(fmaxf(acc2[nt0 * 4 + 0] + b20, 0.f),
                                     fmaxf(acc2[nt0 * 4 + 1] + b21, 0.f));
            A3[kt * 4 + 1] = packbf2(fmaxf(acc2[nt0 * 4 + 2] + b20, 0.f),
                                     fmaxf(acc2[nt0 * 4 + 3] + b21, 0.f));
            A3[kt * 4 + 2] = packbf2(fmaxf(acc2[nt1 * 4 + 0] + b22, 0.f),
                                     fmaxf(acc2[nt1 * 4 + 1] + b23, 0.f));
            A3[kt * 4 + 3] = packbf2(fmaxf(acc2[nt1 * 4 + 2] + b22, 0.f),
                                     fmaxf(acc2[nt1 * 4 + 3] + b23, 0.f));
        }

        float acc3[32];
        #pragma unroll
        for (int i = 0; i < 32; i++) acc3[i] = 0.f;
        #pragma unroll
        for (int kt = 0; kt < 8; kt++) {
            #pragma unroll
            for (int p = 0; p < 4; p++) {
                uint32 b0, b1r, b2r, b3r;
                ldsm4(b0, b1r, b2r, b3r, lmB3 + (uint32)(p * 16 * (KP * 2) + kt * 32));
                mma16816(&acc3[(2 * p) * 4], A3[kt * 4 + 0], A3[kt * 4 + 1],
                         A3[kt * 4 + 2], A3[kt * 4 + 3], b0, b1r);
                mma16816(&acc3[(2 * p + 1) * 4], A3[kt * 4 + 0], A3[kt * 4 + 1],
                         A3[kt * 4 + 2], A3[kt * 4 + 3], b2r, b3r);
            }
        }

        // ---- epilogue: scatter r = photons*sigmoid(acc3+b3) to bin-ordered rows ----
        #pragma unroll
        for (int nt = 0; nt < 8; nt++) {
            const int c0 = nt * 8 + kq;
            float bb0 = sB3[c0], bb1 = sB3[c0 + 1];
            float s0 = sigmoid_mufu(acc3[nt * 4 + 0] + bb0);
            float s1 = sigmoid_mufu(acc3[nt * 4 + 1] + bb1);
            float s2 = sigmoid_mufu(acc3[nt * 4 + 2] + bb0);
            float s3 = sigmoid_mufu(acc3[nt * 4 + 3] + bb1);
            const uint32 w0 = packbf2(ph0 * s0, ph0 * s1);
            const uint32 w1 = packbf2(ph1 * s2, ph1 * s3);
            const int col = nt * 4 + tg;
            if (pm0.x >= 0) g_Rbin[(size_t)pm0.x * 32 + col] = w0;
            if (pm0.y >= 0) g_Rbin[(size_t)pm0.y * 32 + col] = w0;
            if (pm1.x >= 0) g_Rbin[(size_t)pm1.x * 32 + col] = w1;
            if (pm1.y >= 0) g_Rbin[(size_t)pm1.y * 32 + col] = w1;
        }
    }
}

// ---------------- binning kernel (1 electron/thread, 4x parallelism) ----------------
constexpr int BIN_BLOCKS = (N_EL + 255) / 256;   // 1172

__global__ __launch_bounds__(256)
void bin_kernel(const float* __restrict__ zpos, float4* __restrict__ out4) {
    __shared__ int hist[NBIN], sbase[NBIN];
    const int tid = threadIdx.x;
    if (tid < NBIN) hist[tid] = 0;

    // fold output zeroing into first 64 blocks (64*256 float4 = 65536 floats)
    if (blockIdx.x < 64) out4[blockIdx.x * 256 + tid] = make_float4(0.f, 0.f, 0.f, 0.f);
    __syncthreads();

    const int i = blockIdx.x * 256 + tid;
    float zz = 0.f;
    int tlo = -1, thi = -1, slo = 0, shi = 0;
    if (i < N_EL) {
        zz = zpos[i];
        int c = __float2int_rn(zz);
        int lo = max(c - WV_R, 0) >> 5;
        int hi = min(c + WV_R, TICKS - 1) >> 5;
        tlo = lo; slo = atomicAdd(&hist[lo], 1);
        if (hi != lo) { thi = hi; shi = atomicAdd(&hist[hi], 1); }
    }
    __syncthreads();
    if (tid < NBIN) sbase[tid] = atomicAdd(&g_binCnt[tid], hist[tid]);
    __syncthreads();
    if (i < N_EL) {
        int e0 = -1, e1 = -1;
        int p = sbase[tlo] + slo;
        if (p < BCAP) { g_binZ[tlo * BCAP + p] = zz; e0 = tlo * BCAP + p; }
        if (thi >= 0) {
            int p2 = sbase[thi] + shi;
            if (p2 < BCAP) { g_binZ[thi * BCAP + p2] = zz; e1 = thi * BCAP + p2; }
        }
        g_perm[i] = make_int2(e0, e1);
    }
}

// ======================= waveform kernel (R12 version + tail binCnt reset) ==============
constexpr int WV_NSL = 24;
constexpr float CNORM = 0.3989422804f;

constexpr int EST_S = 264;   // u16 row stride (528 B, aligned + conflict-free)
constexpr int RS2_S = 72;    // u16 row stride (144 B, aligned)
constexpr int WOFF_EST = 0;                          // u16[32*264]  = 16896 B
constexpr int WOFF_RS2 = WOFF_EST + 32 * EST_S * 2;  // u16[256*72]  = 36864 B
constexpr int WV_SMEM  = WOFF_RS2 + 256 * RS2_S * 2; // ~52.5 KB

__global__ __launch_bounds__(256, 2)
void waveform_gemm(float* __restrict__ out) {
    extern __shared__ unsigned char sm[];
    u16*    EST  = reinterpret_cast<u16*>(sm + WOFF_EST);
    uint32* RS2w = reinterpret_cast<uint32*>(sm + WOFF_RS2);

    const int tid  = threadIdx.x;
    const int lane = tid & 31;
    const int wid  = tid >> 5;
    const int g    = lane >> 2, tg = lane & 3;
    const int tile = blockIdx.x;
    const int t0   = tile * 32;

    const int cnt = min(g_binCnt[tile], BCAP);
    const int nc  = (cnt + 255) >> 8;       // whole chunks
    const int emax = cnt - 1;

    float C[8];
    #pragma unroll
    for (int i = 0; i < 8; i++) C[i] = 0.f;

    const int mt = wid & 3;       // m-tile (16 sensors)
    const int nh = wid >> 2;      // n-half (16 ticks)

    const int arow = (lane & 7) + ((lane >> 4) << 3);
    const int acol = mt * 16 + ((lane >> 3) & 1) * 8;
    const uint32 lmA = smem_u32(sm + WOFF_RS2) + (uint32)((arow * RS2_S + acol) * 2);
    const int rowB = (lane & 7) + ((lane >> 4) << 3);
    const uint32 lmB = smem_u32(sm + WOFF_EST) +
        (uint32)(((nh * 16 + rowB) * EST_S + (((lane >> 3) & 1) * 8)) * 2);

    for (int c = blockIdx.y; c < nc; c += WV_NSL) {
        const int cb = c << 8;
        const int cend = min(cb + 256, cnt);

        // ---- build E^T: direct gaussian eval, 32 independent EX2s ----
        {
            const int e = cb + tid;
            const float zz = g_binZ[tile * BCAP + min(e, emax)];
            const float cn = (e < cend) ? CNORM : 0.f;
            const float d0 = (float)t0 - zz;
            #pragma unroll
            for (int j = 0; j < 32; j++) {
                float d = d0 + (float)j;
                float ex = __expf(-0.5f * d * d);
                EST[j * EST_S + tid] = __bfloat16_as_ushort(__float2bfloat16_rn(cn * ex));
            }
        }
        // ---- load R rows (sequential, coalesced 128-bit) -> RS2 staging ----
        {
            const uint32* src = g_Rbin + ((size_t)tile * BCAP + cb + wid * 32) * 32;
            const int lrow_in = (lane >> 3);
            const int word = (lane & 7) * 4;
            #pragma unroll
            for (int q = 0; q < 8; q++) {
                const int lrow = q * 4 + lrow_in;   // 0..31 within warp's 32 rows
                uint4 v = *reinterpret_cast<const uint4*>(src + lrow * 32 + word);
                *reinterpret_cast<uint4*>(&RS2w[(wid * 32 + lrow) * (RS2_S / 2) + word]) = v;
            }
        }
        __syncthreads();

        // ---- GEMM: C += R^T @ E over K=256 (A via ldsm.trans, B via ldsm) ----
        #pragma unroll
        for (int ks = 0; ks < 16; ks++) {
            uint32 a0, a1, a2, a3, b0, b1, b2, b3;
            ldsm4t(a0, a1, a2, a3, lmA + (uint32)(ks * 16 * RS2_S * 2));
            ldsm4 (b0, b1, b2, b3, lmB + (uint32)(ks * 32));
            mma16816(&C[0], a0, a1, a2, a3, b0, b1);
            mma16816(&C[4], a0, a1, a2, a3, b2, b3);
        }
        __syncthreads();
    }

    // ---- epilogue: scatter C fragments via atomics ----
    #pragma unroll
    for (int nt = 0; nt < 2; nt++) {
        const int tcol = t0 + (nh * 2 + nt) * 8 + 2 * tg;
        const int srow = mt * 16 + g;
        atomicAdd(&out[srow * 1024 + tcol],           C[nt * 4 + 0]);
        atomicAdd(&out[srow * 1024 + tcol + 1],       C[nt * 4 + 1]);
        atomicAdd(&out[(srow + 8) * 1024 + tcol],     C[nt * 4 + 2]);
        atomicAdd(&out[(srow + 8) * 1024 + tcol + 1], C[nt * 4 + 3]);
    }

    // ---- tail: last y-slice of this tile resets bin counters for the next replay ----
    if (tid == 0) {
        int d = atomicAdd(&g_done[tile], 1);
        if (d == WV_NSL - 1) { g_binCnt[tile] = 0; g_done[tile] = 0; }
    }
}

// ---------------- launch ----------------
extern "C" void kernel_launch(void* const* d_in, const int* in_sizes, int n_in,
                              void* d_out, int out_size) {
    const float*  photons = (const float*)d_in[0];
    const float2* xy      = (const float2*)d_in[1];
    const float*  zpos    = (const float*)d_in[2];
    const float*  W1      = (const float*)d_in[3];
    const float*  b1      = (const float*)d_in[4];
    const float*  W2      = (const float*)d_in[5];
    const float*  b2      = (const float*)d_in[6];
    const float*  W3      = (const float*)d_in[7];
    const float*  b3      = (const float*)d_in[8];
    float* out = (float*)d_out;

    cudaFuncSetAttribute(mlp_kernel, cudaFuncAttributeMaxDynamicSharedMemorySize, MLP_SMEM);
    cudaFuncSetAttribute(waveform_gemm, cudaFuncAttributeMaxDynamicSharedMemorySize, WV_SMEM);

    bin_kernel<<<BIN_BLOCKS, 256>>>(zpos, (float4*)out);
    mlp_kernel<<<MLP_GRID, 256, MLP_SMEM>>>(photons, xy, W1, b1, W2, b2, W3, b3);

    dim3 wgrid(TICKS / 32, WV_NSL);
    waveform_gemm<<<wgrid, 256, WV_SMEM>>>(out);
}

// round 16
// speedup vs baseline: 1.0670x; 1.0127x over previous
#include <cuda_runtime.h>
#include <cuda_bf16.h>
#include <cuda_fp16.h>

typedef unsigned int uint32;
typedef unsigned short u16;

// ---------------- problem constants ----------------
constexpr int N_EL  = 300000;
constexpr int SENS  = 64;
constexpr int TICKS = 1024;
constexpr int HID   = 128;

// ---------------- global scratch ----------------
constexpr int NBIN = 32;       // 32-tick tiles
constexpr int BCAP = 16384;
constexpr int WV_R = 5;        // gaussian inclusion radius (ticks)

__device__ uint32 g_Rbin[(size_t)NBIN * BCAP * 32];  // bin-ordered response bf16x2 (64 MB)
__device__ float  g_binZ[NBIN * BCAP];
__device__ int    g_binCnt[NBIN];
__device__ int    g_done[NBIN];
__device__ int2   g_perm[N_EL];                      // per-electron bin slots (x, y; -1 = none)

// ---------------- helpers ----------------
// bf16 mma (waveform kernel)
__device__ __forceinline__ void mma16816(float* c, uint32 a0, uint32 a1, uint32 a2, uint32 a3,
                                         uint32 b0, uint32 b1) {
    asm volatile(
        "mma.sync.aligned.m16n8k16.row.col.f32.bf16.bf16.f32 "
        "{%0,%1,%2,%3},{%4,%5,%6,%7},{%8,%9},{%0,%1,%2,%3};\n"
        : "+f"(c[0]), "+f"(c[1]), "+f"(c[2]), "+f"(c[3])
        : "r"(a0), "r"(a1), "r"(a2), "r"(a3), "r"(b0), "r"(b1));
}
// fp16 inputs, f32 accum (MLP GEMM1)
__device__ __forceinline__ void mma_f32h(float* c, uint32 a0, uint32 a1, uint32 a2, uint32 a3,
                                         uint32 b0, uint32 b1) {
    asm volatile(
        "mma.sync.aligned.m16n8k16.row.col.f32.f16.f16.f32 "
        "{%0,%1,%2,%3},{%4,%5,%6,%7},{%8,%9},{%0,%1,%2,%3};\n"
        : "+f"(c[0]), "+f"(c[1]), "+f"(c[2]), "+f"(c[3])
        : "r"(a0), "r"(a1), "r"(a2), "r"(a3), "r"(b0), "r"(b1));
}
// fp16 inputs, fp16 accum (MLP GEMM2/3) — D is 2x f16x2
__device__ __forceinline__ void mma_h(uint32* c, uint32 a0, uint32 a1, uint32 a2, uint32 a3,
                                      uint32 b0, uint32 b1) {
    asm volatile(
        "mma.sync.aligned.m16n8k16.row.col.f16.f16.f16.f16 "
        "{%0,%1},{%2,%3,%4,%5},{%6,%7},{%0,%1};\n"
        : "+r"(c[0]), "+r"(c[1])
        : "r"(a0), "r"(a1), "r"(a2), "r"(a3), "r"(b0), "r"(b1));
}

__device__ __forceinline__ void ldsm4(uint32& r0, uint32& r1, uint32& r2, uint32& r3,
                                      uint32 addr) {
    asm volatile("ldmatrix.sync.aligned.m8n8.x4.shared.b16 {%0,%1,%2,%3}, [%4];"
        : "=r"(r0), "=r"(r1), "=r"(r2), "=r"(r3) : "r"(addr));
}
__device__ __forceinline__ void ldsm4t(uint32& r0, uint32& r1, uint32& r2, uint32& r3,
                                       uint32 addr) {
    asm volatile("ldmatrix.sync.aligned.m8n8.x4.trans.shared.b16 {%0,%1,%2,%3}, [%4];"
        : "=r"(r0), "=r"(r1), "=r"(r2), "=r"(r3) : "r"(addr));
}
__device__ __forceinline__ uint32 smem_u32(const void* p) {
    uint32 a;
    asm("{ .reg .u64 t; cvta.to.shared.u64 t, %1; cvt.u32.u64 %0, t; }" : "=r"(a) : "l"(p));
    return a;
}
__device__ __forceinline__ uint32 packbf2(float a, float b) {
    __nv_bfloat162 t = __floats2bfloat162_rn(a, b);
    return *reinterpret_cast<uint32*>(&t);
}
__device__ __forceinline__ uint32 packh2(float a, float b) {
    __half2 t = __floats2half2_rn(a, b);
    return *reinterpret_cast<uint32*>(&t);
}
__device__ __forceinline__ uint32 hradd2(uint32 a, uint32 b) {   // relu(a + b), half2
    __half2 r = __hmax2(__hadd2(*reinterpret_cast<__half2*>(&a),
                                *reinterpret_cast<__half2*>(&b)),
                        __half2(__half(0.f), __half(0.f)));
    return *reinterpret_cast<uint32*>(&r);
}

// MUFU-based sigmoid: EX2 + RCP (~5 issues)
__device__ __forceinline__ float sigmoid_mufu(float x) {
    return __fdividef(1.f, 1.f + __expf(-x));
}

// ======================= MLP kernel (fp16-accum GEMM2/3) =======================
constexpr int KP  = 136;
constexpr int NWT = N_EL / 16;       // 18750
constexpr int MLP_GRID = 296;

constexpr int OFF_W2T = 0;                          // [128][KP] f16 = 34816 B
constexpr int OFF_W3T = OFF_W2T + HID * KP * 2;     // [64][KP]  f16 = 17408 B
constexpr int OFF_W1E = OFF_W3T + SENS * KP * 2;    // [128][16] f16 = 4096 B
constexpr int OFF_B2H = OFF_W1E + 128 * 16 * 2;     // uint32[64] packed half2 pairs
constexpr int OFF_B3H = OFF_B2H + 64 * 4;           // uint32[32]
constexpr int MLP_SMEM = OFF_B3H + 32 * 4;          // ~56.8 KB

__global__ __launch_bounds__(256, 2)
void mlp_kernel(const float* __restrict__ photons,
                const float2* __restrict__ xy,
                const float* __restrict__ W1, const float* __restrict__ b1,
                const float* __restrict__ W2, const float* __restrict__ b2,
                const float* __restrict__ W3, const float* __restrict__ b3) {
    extern __shared__ unsigned char sm[];
    __half* sW2t = reinterpret_cast<__half*>(sm + OFF_W2T);
    __half* sW3t = reinterpret_cast<__half*>(sm + OFF_W3T);
    __half* sW1e = reinterpret_cast<__half*>(sm + OFF_W1E);
    uint32* sB2h = reinterpret_cast<uint32*>(sm + OFF_B2H);
    uint32* sB3h = reinterpret_cast<uint32*>(sm + OFF_B3H);

    const int tid = threadIdx.x;
    for (int i = tid; i < HID * HID; i += 256) {
        int k = i >> 7, n = i & 127;
        sW2t[n * KP + k] = __float2half_rn(W2[i]);
    }
    for (int i = tid; i < HID * SENS; i += 256) {
        int k = i >> 6, n = i & 63;
        sW3t[n * KP + k] = __float2half_rn(W3[i]);
    }
    for (int i = tid; i < 128 * 16; i += 256) {
        int n = i >> 4, k = i & 15;
        float v = (k == 0) ? W1[n] : (k == 1) ? W1[128 + n] : (k == 2) ? b1[n] : 0.f;
        sW1e[i] = __float2half_rn(v);
    }
    if (tid < 64) sB2h[tid] = packh2(b2[2 * tid], b2[2 * tid + 1]);
    if (tid < 32) sB3h[tid] = packh2(b3[2 * tid], b3[2 * tid + 1]);
    __syncthreads();

    const int wid = tid >> 5, lane = tid & 31;
    const int g = lane >> 2, tg = lane & 3;
    const int kq = tg * 2;

    const int row_in = (lane & 7) + ((lane >> 4) << 3);
    const int k8off  = (lane >> 3) & 1;
    const uint32 lmB2 = smem_u32(sW2t) + (uint32)(row_in * (KP * 2) + k8off * 16);
    const uint32 lmB3 = smem_u32(sW3t) + (uint32)(row_in * (KP * 2) + k8off * 16);

    const int wslot   = blockIdx.x * 8 + wid;
    const int wstride = gridDim.x * 8;

    for (int wt = wslot; wt < NWT; wt += wstride) {
        const int r0 = wt * 16 + g, r1 = r0 + 8;
        const float2 p0 = xy[r0], p1 = xy[r1];
        const float ph0 = photons[r0], ph1 = photons[r1];
        const int2 pm0 = g_perm[r0];
        const int2 pm1 = g_perm[r1];

        // ---- GEMM1: h1 = relu([x,y,1]@W1ext), f16 inputs, f32 accum ----
        float acc1[64];
        #pragma unroll
        for (int i = 0; i < 64; i++) acc1[i] = 0.f;
        const uint32 oneh = 0x00003C00u;    // half2 (1.0, 0.0)
        const uint32 xa0 = (tg == 0) ? packh2(p0.x, p0.y) : ((tg == 1) ? oneh : 0u);
        const uint32 xa1 = (tg == 0) ? packh2(p1.x, p1.y) : ((tg == 1) ? oneh : 0u);
        #pragma unroll
        for (int nt = 0; nt < 16; nt++) {
            uint32 b0 = *reinterpret_cast<const uint32*>(sW1e + (nt * 8 + g) * 16 + kq);
            mma_f32h(&acc1[nt * 4], xa0, xa1, 0u, 0u, b0, 0u);
        }

        uint32 A2[32];
        #pragma unroll
        for (int kt = 0; kt < 8; kt++) {
            A2[kt * 4 + 0] = packh2(fmaxf(acc1[8 * kt + 0], 0.f), fmaxf(acc1[8 * kt + 1], 0.f));
            A2[kt * 4 + 1] = packh2(fmaxf(acc1[8 * kt + 2], 0.f), fmaxf(acc1[8 * kt + 3], 0.f));
            A2[kt * 4 + 2] = packh2(fmaxf(acc1[8 * kt + 4], 0.f), fmaxf(acc1[8 * kt + 5], 0.f));
            A2[kt * 4 + 3] = packh2(fmaxf(acc1[8 * kt + 6], 0.f), fmaxf(acc1[8 * kt + 7], 0.f));
        }

        // ---- GEMM2: fp16 accumulate; 16 n8-tiles x 2 regs ----
        uint32 acc2h[32];
        #pragma unroll
        for (int i = 0; i < 32; i++) acc2h[i] = 0u;
        #pragma unroll
        for (int kt = 0; kt < 8; kt++) {
            #pragma unroll
            for (int p = 0; p < 8; p++) {
                uint32 b0, b1r, b2r, b3r;
                ldsm4(b0, b1r, b2r, b3r, lmB2 + (uint32)(p * 16 * (KP * 2) + kt * 32));
                mma_h(&acc2h[(2 * p) * 2], A2[kt * 4 + 0], A2[kt * 4 + 1],
                      A2[kt * 4 + 2], A2[kt * 4 + 3], b0, b1r);
                mma_h(&acc2h[(2 * p + 1) * 2], A2[kt * 4 + 0], A2[kt * 4 + 1],
                      A2[kt * 4 + 2], A2[kt * 4 + 3], b2r, b3r);
            }
        }

        // ---- repack: A3 = relu(acc2h + b2), half2 ops; D-packing == A-fragment ----
        uint32 A3[32];
        #pragma unroll
        for (int kt = 0; kt < 8; kt++) {
            const int nt0 = 2 * kt, nt1 = nt0 + 1;
            const uint32 bp0 = sB2h[nt0 * 4 + tg];
            const uint32 bp1 = sB2h[nt1 * 4 + tg];
            A3[kt * 4 + 0] = hradd2(acc2h[nt0 * 2 + 0], bp0);
            A3[kt * 4 + 1] = hradd2(acc2h[nt0 * 2 + 1], bp0);
            A3[kt * 4 + 2] = hradd2(acc2h[nt1 * 2 + 0], bp1);
            A3[kt * 4 + 3] = hradd2(acc2h[nt1 * 2 + 1], bp1);
        }

        // ---- GEMM3: fp16 accumulate; 8 n8-tiles x 2 regs ----
        uint32 acc3h[16];
        #pragma unroll
        for (int i = 0; i < 16; i++) acc3h[i] = 0u;
        #pragma unroll
        for (int kt = 0; kt < 8; kt++) {
            #pragma unroll
            for (int p = 0; p < 4; p++) {
                uint32 b0, b1r, b2r, b3r;
                ldsm4(b0, b1r, b2r, b3r, lmB3 + (uint32)(p * 16 * (KP * 2) + kt * 32));
                mma_h(&acc3h[(2 * p) * 2], A3[kt * 4 + 0], A3[kt * 4 + 1],
                      A3[kt * 4 + 2], A3[kt * 4 + 3], b0, b1r);
                mma_h(&acc3h[(2 * p + 1) * 2], A3[kt * 4 + 0], A3[kt * 4 + 1],
                      A3[kt * 4 + 2], A3[kt * 4 + 3], b2r, b3r);
            }
        }

        // ---- epilogue: r = photons * sigmoid(acc3h + b3) -> bin-ordered bf16x2 ----
        #pragma unroll
        for (int nt = 0; nt < 8; nt++) {
            const uint32 bp = sB3h[nt * 4 + tg];
            uint32 u0 = hradd2(acc3h[nt * 2 + 0], bp);  // relu is harmless pre-sigmoid? NO.
            uint32 u1;
            // careful: need plain add (no relu) before sigmoid
            {
                __half2 v0 = __hadd2(*reinterpret_cast<__half2*>(&acc3h[nt * 2 + 0]),
                                     *reinterpret_cast<const __half2*>(&bp));
                __half2 v1 = __hadd2(*reinterpret_cast<__half2*>(&acc3h[nt * 2 + 1]),
                                     *reinterpret_cast<const __half2*>(&bp));
                u0 = *reinterpret_cast<uint32*>(&v0);
                u1 = *reinterpret_cast<uint32*>(&v1);
            }
            float2 f0 = __half22float2(*reinterpret_cast<__half2*>(&u0));
            float2 f1 = __half22float2(*reinterpret_cast<__half2*>(&u1));
            float s0 = sigmoid_mufu(f0.x), s1 = sigmoid_mufu(f0.y);
            float s2 = sigmoid_mufu(f1.x), s3 = sigmoid_mufu(f1.y);
            const uint32 w0 = packbf2(ph0 * s0, ph0 * s1);
            const uint32 w1 = packbf2(ph1 * s2, ph1 * s3);
            const int col = nt * 4 + tg;
            if (pm0.x >= 0) g_Rbin[(size_t)pm0.x * 32 + col] = w0;
            if (pm0.y >= 0) g_Rbin[(size_t)pm0.y * 32 + col] = w0;
            if (pm1.x >= 0) g_Rbin[(size_t)pm1.x * 32 + col] = w1;
            if (pm1.y >= 0) g_Rbin[(size_t)pm1.y * 32 + col] = w1;
        }
    }
}

// ---------------- binning kernel (1 electron/thread) ----------------
constexpr int BIN_BLOCKS = (N_EL + 255) / 256;   // 1172

__global__ __launch_bounds__(256)
void bin_kernel(const float* __restrict__ zpos, float4* __restrict__ out4) {
    __shared__ int hist[NBIN], sbase[NBIN];
    const int tid = threadIdx.x;
    if (tid < NBIN) hist[tid] = 0;

    if (blockIdx.x < 64) out4[blockIdx.x * 256 + tid] = make_float4(0.f, 0.f, 0.f, 0.f);
    __syncthreads();

    const int i = blockIdx.x * 256 + tid;
    float zz = 0.f;
    int tlo = -1, thi = -1, slo = 0, shi = 0;
    if (i < N_EL) {
        zz = zpos[i];
        int c = __float2int_rn(zz);
        int lo = max(c - WV_R, 0) >> 5;
        int hi = min(c + WV_R, TICKS - 1) >> 5;
        tlo = lo; slo = atomicAdd(&hist[lo], 1);
        if (hi != lo) { thi = hi; shi = atomicAdd(&hist[hi], 1); }
    }
    __syncthreads();
    if (tid < NBIN) sbase[tid] = atomicAdd(&g_binCnt[tid], hist[tid]);
    __syncthreads();
    if (i < N_EL) {
        int e0 = -1, e1 = -1;
        int p = sbase[tlo] + slo;
        if (p < BCAP) { g_binZ[tlo * BCAP + p] = zz; e0 = tlo * BCAP + p; }
        if (thi >= 0) {
            int p2 = sbase[thi] + shi;
            if (p2 < BCAP) { g_binZ[thi * BCAP + p2] = zz; e1 = thi * BCAP + p2; }
        }
        g_perm[i] = make_int2(e0, e1);
    }
}

// ======================= waveform kernel (R12 version + tail binCnt reset) ==============
constexpr int WV_NSL = 24;
constexpr float CNORM = 0.3989422804f;

constexpr int EST_S = 264;   // u16 row stride (528 B, aligned + conflict-free)
constexpr int RS2_S = 72;    // u16 row stride (144 B, aligned)
constexpr int WOFF_EST = 0;                          // u16[32*264]  = 16896 B
constexpr int WOFF_RS2 = WOFF_EST + 32 * EST_S * 2;  // u16[256*72]  = 36864 B
constexpr int WV_SMEM  = WOFF_RS2 + 256 * RS2_S * 2; // ~52.5 KB

__global__ __launch_bounds__(256, 2)
void waveform_gemm(float* __restrict__ out) {
    extern __shared__ unsigned char sm[];
    u16*    EST  = reinterpret_cast<u16*>(sm + WOFF_EST);
    uint32* RS2w = reinterpret_cast<uint32*>(sm + WOFF_RS2);

    const int tid  = threadIdx.x;
    const int lane = tid & 31;
    const int wid  = tid >> 5;
    const int g    = lane >> 2, tg = lane & 3;
    const int tile = blockIdx.x;
    const int t0   = tile * 32;

    const int cnt = min(g_binCnt[tile], BCAP);
    const int nc  = (cnt + 255) >> 8;       // whole chunks
    const int emax = cnt - 1;

    float C[8];
    #pragma unroll
    for (int i = 0; i < 8; i++) C[i] = 0.f;

    const int mt = wid & 3;       // m-tile (16 sensors)
    const int nh = wid >> 2;      // n-half (16 ticks)

    const int arow = (lane & 7) + ((lane >> 4) << 3);
    const int acol = mt * 16 + ((lane >> 3) & 1) * 8;
    const uint32 lmA = smem_u32(sm + WOFF_RS2) + (uint32)((arow * RS2_S + acol) * 2);
    const int rowB = (lane & 7) + ((lane >> 4) << 3);
    const uint32 lmB = smem_u32(sm + WOFF_EST) +
        (uint32)(((nh * 16 + rowB) * EST_S + (((lane >> 3) & 1) * 8)) * 2);

    for (int c = blockIdx.y; c < nc; c += WV_NSL) {
        const int cb = c << 8;
        const int cend = min(cb + 256, cnt);

        {
            const int e = cb + tid;
            const float zz = g_binZ[tile * BCAP + min(e, emax)];
            const float cn = (e < cend) ? CNORM : 0.f;
            const float d0 = (float)t0 - zz;
            #pragma unroll
            for (int j = 0; j < 32; j++) {
                float d = d0 + (float)j;
                float ex = __expf(-0.5f * d * d);
                EST[j * EST_S + tid] = __bfloat16_as_ushort(__float2bfloat16_rn(cn * ex));
            }
        }
        {
            const uint32* src = g_Rbin + ((size_t)tile * BCAP + cb + wid * 32) * 32;
            const int lrow_in = (lane >> 3);
            const int word = (lane & 7) * 4;
            #pragma unroll
            for (int q = 0; q < 8; q++) {
                const int lrow = q * 4 + lrow_in;
                uint4 v = *reinterpret_cast<const uint4*>(src + lrow * 32 + word);
                *reinterpret_cast<uint4*>(&RS2w[(wid * 32 + lrow) * (RS2_S / 2) + word]) = v;
            }
        }
        __syncthreads();

        #pragma unroll
        for (int ks = 0; ks < 16; ks++) {
            uint32 a0, a1, a2, a3, b0, b1, b2, b3;
            ldsm4t(a0, a1, a2, a3, lmA + (uint32)(ks * 16 * RS2_S * 2));
            ldsm4 (b0, b1, b2, b3, lmB + (uint32)(ks * 32));
            mma16816(&C[0], a0, a1, a2, a3, b0, b1);
            mma16816(&C[4], a0, a1, a2, a3, b2, b3);
        }
        __syncthreads();
    }

    #pragma unroll
    for (int nt = 0; nt < 2; nt++) {
        const int tcol = t0 + (nh * 2 + nt) * 8 + 2 * tg;
        const int srow = mt * 16 + g;
        atomicAdd(&out[srow * 1024 + tcol],           C[nt * 4 + 0]);
        atomicAdd(&out[srow * 1024 + tcol + 1],       C[nt * 4 + 1]);
        atomicAdd(&out[(srow + 8) * 1024 + tcol],     C[nt * 4 + 2]);
        atomicAdd(&out[(srow + 8) * 1024 + tcol + 1], C[nt * 4 + 3]);
    }

    if (tid == 0) {
        int d = atomicAdd(&g_done[tile], 1);
        if (d == WV_NSL - 1) { g_binCnt[tile] = 0; g_done[tile] = 0; }
    }
}

// ---------------- launch ----------------
extern "C" void kernel_launch(void* const* d_in, const int* in_sizes, int n_in,
                              void* d_out, int out_size) {
    const float*  photons = (const float*)d_in[0];
    const float2* xy      = (const float2*)d_in[1];
    const float*  zpos    = (const float*)d_in[2];
    const float*  W1      = (const float*)d_in[3];
    const float*  b1      = (const float*)d_in[4];
    const float*  W2      = (const float*)d_in[5];
    const float*  b2      = (const float*)d_in[6];
    const float*  W3      = (const float*)d_in[7];
    const float*  b3      = (const float*)d_in[8];
    float* out = (float*)d_out;

    cudaFuncSetAttribute(mlp_kernel, cudaFuncAttributeMaxDynamicSharedMemorySize, MLP_SMEM);
    cudaFuncSetAttribute(waveform_gemm, cudaFuncAttributeMaxDynamicSharedMemorySize, WV_SMEM);

    bin_kernel<<<BIN_BLOCKS, 256>>>(zpos, (float4*)out);
    mlp_kernel<<<MLP_GRID, 256, MLP_SMEM>>>(photons, xy, W1, b1, W2, b2, W3, b3);

    dim3 wgrid(TICKS / 32, WV_NSL);
    waveform_gemm<<<wgrid, 256, WV_SMEM>>>(out);
}

// round 17
// speedup vs baseline: 1.0811x; 1.0132x over previous
#include <cuda_runtime.h>
#include <cuda_bf16.h>
#include <cuda_fp16.h>

typedef unsigned int uint32;
typedef unsigned short u16;

// ---------------- problem constants ----------------
constexpr int N_EL  = 300000;
constexpr int SENS  = 64;
constexpr int TICKS = 1024;
constexpr int HID   = 128;

// ---------------- global scratch ----------------
constexpr int NBIN = 32;       // 32-tick tiles
constexpr int BCAP = 16384;
constexpr int WV_R = 5;        // gaussian inclusion radius (ticks)

__device__ uint32 g_Rbin[(size_t)NBIN * BCAP * 32];  // bin-ordered response bf16x2 (64 MB)
__device__ float  g_binZ[NBIN * BCAP];
__device__ int    g_binCnt[NBIN];
__device__ int    g_done[NBIN];
__device__ int2   g_perm[N_EL];                      // per-electron bin slots (x, y; -1 = none)
__device__ int    g_bar;                             // monotonic epoch barrier counter

// ---------------- helpers ----------------
__device__ __forceinline__ void mma16816(float* c, uint32 a0, uint32 a1, uint32 a2, uint32 a3,
                                         uint32 b0, uint32 b1) {
    asm volatile(
        "mma.sync.aligned.m16n8k16.row.col.f32.bf16.bf16.f32 "
        "{%0,%1,%2,%3},{%4,%5,%6,%7},{%8,%9},{%0,%1,%2,%3};\n"
        : "+f"(c[0]), "+f"(c[1]), "+f"(c[2]), "+f"(c[3])
        : "r"(a0), "r"(a1), "r"(a2), "r"(a3), "r"(b0), "r"(b1));
}
__device__ __forceinline__ void mma_f32h(float* c, uint32 a0, uint32 a1, uint32 a2, uint32 a3,
                                         uint32 b0, uint32 b1) {
    asm volatile(
        "mma.sync.aligned.m16n8k16.row.col.f32.f16.f16.f32 "
        "{%0,%1,%2,%3},{%4,%5,%6,%7},{%8,%9},{%0,%1,%2,%3};\n"
        : "+f"(c[0]), "+f"(c[1]), "+f"(c[2]), "+f"(c[3])
        : "r"(a0), "r"(a1), "r"(a2), "r"(a3), "r"(b0), "r"(b1));
}
__device__ __forceinline__ void mma_h(uint32* c, uint32 a0, uint32 a1, uint32 a2, uint32 a3,
                                      uint32 b0, uint32 b1) {
    asm volatile(
        "mma.sync.aligned.m16n8k16.row.col.f16.f16.f16.f16 "
        "{%0,%1},{%2,%3,%4,%5},{%6,%7},{%0,%1};\n"
        : "+r"(c[0]), "+r"(c[1])
        : "r"(a0), "r"(a1), "r"(a2), "r"(a3), "r"(b0), "r"(b1));
}

__device__ __forceinline__ void ldsm4(uint32& r0, uint32& r1, uint32& r2, uint32& r3,
                                      uint32 addr) {
    asm volatile("ldmatrix.sync.aligned.m8n8.x4.shared.b16 {%0,%1,%2,%3}, [%4];"
        : "=r"(r0), "=r"(r1), "=r"(r2), "=r"(r3) : "r"(addr));
}
__device__ __forceinline__ void ldsm4t(uint32& r0, uint32& r1, uint32& r2, uint32& r3,
                                       uint32 addr) {
    asm volatile("ldmatrix.sync.aligned.m8n8.x4.trans.shared.b16 {%0,%1,%2,%3}, [%4];"
        : "=r"(r0), "=r"(r1), "=r"(r2), "=r"(r3) : "r"(addr));
}
__device__ __forceinline__ uint32 smem_u32(const void* p) {
    uint32 a;
    asm("{ .reg .u64 t; cvta.to.shared.u64 t, %1; cvt.u32.u64 %0, t; }" : "=r"(a) : "l"(p));
    return a;
}
__device__ __forceinline__ uint32 packbf2(float a, float b) {
    __nv_bfloat162 t = __floats2bfloat162_rn(a, b);
    return *reinterpret_cast<uint32*>(&t);
}
__device__ __forceinline__ uint32 packh2(float a, float b) {
    __half2 t = __floats2half2_rn(a, b);
    return *reinterpret_cast<uint32*>(&t);
}
__device__ __forceinline__ uint32 hradd2(uint32 a, uint32 b) {   // relu(a + b), half2
    __half2 r = __hmax2(__hadd2(*reinterpret_cast<__half2*>(&a),
                                *reinterpret_cast<__half2*>(&b)),
                        __half2(__half(0.f), __half(0.f)));
    return *reinterpret_cast<uint32*>(&r);
}
__device__ __forceinline__ float sigmoid_mufu(float x) {
    return __fdividef(1.f, 1.f + __expf(-x));
}

// ======================= fused bin + MLP kernel =======================
constexpr int KP  = 136;
constexpr int NWT = N_EL / 16;       // 18750
constexpr int MLP_GRID = 296;        // exactly 2 CTAs/SM resident -> barrier is safe

constexpr int OFF_W2T = 0;                          // [128][KP] f16 = 34816 B
constexpr int OFF_W3T = OFF_W2T + HID * KP * 2;     // [64][KP]  f16 = 17408 B
constexpr int OFF_W1E = OFF_W3T + SENS * KP * 2;    // [128][16] f16 = 4096 B
constexpr int OFF_B2H = OFF_W1E + 128 * 16 * 2;     // uint32[64]
constexpr int OFF_B3H = OFF_B2H + 64 * 4;           // uint32[32]
constexpr int MLP_SMEM = OFF_B3H + 32 * 4;          // ~56.8 KB

__global__ __launch_bounds__(256, 2)
void mlp_kernel(const float* __restrict__ zpos, float4* __restrict__ out4,
                const float* __restrict__ photons,
                const float2* __restrict__ xy,
                const float* __restrict__ W1, const float* __restrict__ b1,
                const float* __restrict__ W2, const float* __restrict__ b2,
                const float* __restrict__ W3, const float* __restrict__ b3) {
    extern __shared__ unsigned char sm[];
    const int tid = threadIdx.x;

    // ======== Phase A: binning (uses start of smem as hist; done before staging) =======
    {
        int* hist  = reinterpret_cast<int*>(sm);
        int* sbase = hist + NBIN;
        if (tid < NBIN) hist[tid] = 0;
        if (blockIdx.x < 64) out4[blockIdx.x * 256 + tid] = make_float4(0.f, 0.f, 0.f, 0.f);
        __syncthreads();

        const int ebase = blockIdx.x * 1024;
        float zz[4];
        int tlo[4], thi[4], slo[4], shi[4];
        #pragma unroll
        for (int q = 0; q < 4; q++) {
            const int i = ebase + q * 256 + tid;
            tlo[q] = -1; thi[q] = -1;
            if (i < N_EL) {
                zz[q] = zpos[i];
                int c = __float2int_rn(zz[q]);
                int lo = max(c - WV_R, 0) >> 5;
                int hi = min(c + WV_R, TICKS - 1) >> 5;
                tlo[q] = lo; slo[q] = atomicAdd(&hist[lo], 1);
                if (hi != lo) { thi[q] = hi; shi[q] = atomicAdd(&hist[hi], 1); }
            }
        }
        __syncthreads();
        if (tid < NBIN) sbase[tid] = atomicAdd(&g_binCnt[tid], hist[tid]);
        __syncthreads();
        #pragma unroll
        for (int q = 0; q < 4; q++) {
            const int i = ebase + q * 256 + tid;
            if (tlo[q] >= 0) {
                int e0 = -1, e1 = -1;
                int p = sbase[tlo[q]] + slo[q];
                if (p < BCAP) { g_binZ[tlo[q] * BCAP + p] = zz[q]; e0 = tlo[q] * BCAP + p; }
                if (thi[q] >= 0) {
                    int p2 = sbase[thi[q]] + shi[q];
                    if (p2 < BCAP) { g_binZ[thi[q] * BCAP + p2] = zz[q]; e1 = thi[q] * BCAP + p2; }
                }
                g_perm[i] = make_int2(e0, e1);
            }
        }
        __threadfence();
        __syncthreads();
    }
    // arrive on epoch barrier (monotonic; replay-safe)
    int bar_target = 0;
    if (tid == 0) {
        int my = atomicAdd(&g_bar, 1);
        bar_target = (my / MLP_GRID + 1) * MLP_GRID;
    }

    // ======== Phase B: weight staging (independent of bin; overlaps other blocks) ======
    __half* sW2t = reinterpret_cast<__half*>(sm + OFF_W2T);
    __half* sW3t = reinterpret_cast<__half*>(sm + OFF_W3T);
    __half* sW1e = reinterpret_cast<__half*>(sm + OFF_W1E);
    uint32* sB2h = reinterpret_cast<uint32*>(sm + OFF_B2H);
    uint32* sB3h = reinterpret_cast<uint32*>(sm + OFF_B3H);

    for (int i = tid; i < HID * HID; i += 256) {
        int k = i >> 7, n = i & 127;
        sW2t[n * KP + k] = __float2half_rn(W2[i]);
    }
    for (int i = tid; i < HID * SENS; i += 256) {
        int k = i >> 6, n = i & 63;
        sW3t[n * KP + k] = __float2half_rn(W3[i]);
    }
    for (int i = tid; i < 128 * 16; i += 256) {
        int n = i >> 4, k = i & 15;
        float v = (k == 0) ? W1[n] : (k == 1) ? W1[128 + n] : (k == 2) ? b1[n] : 0.f;
        sW1e[i] = __float2half_rn(v);
    }
    if (tid < 64) sB2h[tid] = packh2(b2[2 * tid], b2[2 * tid + 1]);
    if (tid < 32) sB3h[tid] = packh2(b3[2 * tid], b3[2 * tid + 1]);

    // ======== wait for all blocks' binning (g_perm complete) ========
    if (tid == 0) {
        while (atomicAdd(&g_bar, 0) < bar_target) { }
    }
    __syncthreads();
    __threadfence();

    // ======== Phase C: MLP main loop (R16 core, fp16-accum GEMM2/3) ========
    const int wid = tid >> 5, lane = tid & 31;
    const int g = lane >> 2, tg = lane & 3;
    const int kq = tg * 2;

    const int row_in = (lane & 7) + ((lane >> 4) << 3);
    const int k8off  = (lane >> 3) & 1;
    const uint32 lmB2 = smem_u32(sW2t) + (uint32)(row_in * (KP * 2) + k8off * 16);
    const uint32 lmB3 = smem_u32(sW3t) + (uint32)(row_in * (KP * 2) + k8off * 16);

    const int wslot   = blockIdx.x * 8 + wid;
    const int wstride = gridDim.x * 8;

    for (int wt = wslot; wt < NWT; wt += wstride) {
        const int r0 = wt * 16 + g, r1 = r0 + 8;
        const float2 p0 = xy[r0], p1 = xy[r1];
        const float ph0 = photons[r0], ph1 = photons[r1];
        const int2 pm0 = g_perm[r0];
        const int2 pm1 = g_perm[r1];

        float acc1[64];
        #pragma unroll
        for (int i = 0; i < 64; i++) acc1[i] = 0.f;
        const uint32 oneh = 0x00003C00u;
        const uint32 xa0 = (tg == 0) ? packh2(p0.x, p0.y) : ((tg == 1) ? oneh : 0u);
        const uint32 xa1 = (tg == 0) ? packh2(p1.x, p1.y) : ((tg == 1) ? oneh : 0u);
        #pragma unroll
        for (int nt = 0; nt < 16; nt++) {
            uint32 b0 = *reinterpret_cast<const uint32*>(sW1e + (nt * 8 + g) * 16 + kq);
            mma_f32h(&acc1[nt * 4], xa0, xa1, 0u, 0u, b0, 0u);
        }

        uint32 A2[32];
        #pragma unroll
        for (int kt = 0; kt < 8; kt++) {
            A2[kt * 4 + 0] = packh2(fmaxf(acc1[8 * kt + 0], 0.f), fmaxf(acc1[8 * kt + 1], 0.f));
            A2[kt * 4 + 1] = packh2(fmaxf(acc1[8 * kt + 2], 0.f), fmaxf(acc1[8 * kt + 3], 0.f));
            A2[kt * 4 + 2] = packh2(fmaxf(acc1[8 * kt + 4], 0.f), fmaxf(acc1[8 * kt + 5], 0.f));
            A2[kt * 4 + 3] = packh2(fmaxf(acc1[8 * kt + 6], 0.f), fmaxf(acc1[8 * kt + 7], 0.f));
        }

        uint32 acc2h[32];
        #pragma unroll
        for (int i = 0; i < 32; i++) acc2h[i] = 0u;
        #pragma unroll
        for (int kt = 0; kt < 8; kt++) {
            #pragma unroll
            for (int p = 0; p < 8; p++) {
                uint32 b0, b1r, b2r, b3r;
                ldsm4(b0, b1r, b2r, b3r, lmB2 + (uint32)(p * 16 * (KP * 2) + kt * 32));
                mma_h(&acc2h[(2 * p) * 2], A2[kt * 4 + 0], A2[kt * 4 + 1],
                      A2[kt * 4 + 2], A2[kt * 4 + 3], b0, b1r);
                mma_h(&acc2h[(2 * p + 1) * 2], A2[kt * 4 + 0], A2[kt * 4 + 1],
                      A2[kt * 4 + 2], A2[kt * 4 + 3], b2r, b3r);
            }
        }

        uint32 A3[32];
        #pragma unroll
        for (int kt = 0; kt < 8; kt++) {
            const int nt0 = 2 * kt, nt1 = nt0 + 1;
            const uint32 bp0 = sB2h[nt0 * 4 + tg];
            const uint32 bp1 = sB2h[nt1 * 4 + tg];
            A3[kt * 4 + 0] = hradd2(acc2h[nt0 * 2 + 0], bp0);
            A3[kt * 4 + 1] = hradd2(acc2h[nt0 * 2 + 1], bp0);
            A3[kt * 4 + 2] = hradd2(acc2h[nt1 * 2 + 0], bp1);
            A3[kt * 4 + 3] = hradd2(acc2h[nt1 * 2 + 1], bp1);
        }

        uint32 acc3h[16];
        #pragma unroll
        for (int i = 0; i < 16; i++) acc3h[i] = 0u;
        #pragma unroll
        for (int kt = 0; kt < 8; kt++) {
            #pragma unroll
            for (int p = 0; p < 4; p++) {
                uint32 b0, b1r, b2r, b3r;
                ldsm4(b0, b1r, b2r, b3r, lmB3 + (uint32)(p * 16 * (KP * 2) + kt * 32));
                mma_h(&acc3h[(2 * p) * 2], A3[kt * 4 + 0], A3[kt * 4 + 1],
                      A3[kt * 4 + 2], A3[kt * 4 + 3], b0, b1r);
                mma_h(&acc3h[(2 * p + 1) * 2], A3[kt * 4 + 0], A3[kt * 4 + 1],
                      A3[kt * 4 + 2], A3[kt * 4 + 3], b2r, b3r);
            }
        }

        #pragma unroll
        for (int nt = 0; nt < 8; nt++) {
            const uint32 bp = sB3h[nt * 4 + tg];
            __half2 v0 = __hadd2(*reinterpret_cast<__half2*>(&acc3h[nt * 2 + 0]),
                                 *reinterpret_cast<const __half2*>(&bp));
            __half2 v1 = __hadd2(*reinterpret_cast<__half2*>(&acc3h[nt * 2 + 1]),
                                 *reinterpret_cast<const __half2*>(&bp));
            float2 f0 = __half22float2(v0);
            float2 f1 = __half22float2(v1);
            float s0 = sigmoid_mufu(f0.x), s1 = sigmoid_mufu(f0.y);
            float s2 = sigmoid_mufu(f1.x), s3 = sigmoid_mufu(f1.y);
            const uint32 w0 = packbf2(ph0 * s0, ph0 * s1);
            const uint32 w1 = packbf2(ph1 * s2, ph1 * s3);
            const int col = nt * 4 + tg;
            if (pm0.x >= 0) g_Rbin[(size_t)pm0.x * 32 + col] = w0;
            if (pm0.y >= 0) g_Rbin[(size_t)pm0.y * 32 + col] = w0;
            if (pm1.x >= 0) g_Rbin[(size_t)pm1.x * 32 + col] = w1;
            if (pm1.y >= 0) g_Rbin[(size_t)pm1.y * 32 + col] = w1;
        }
    }
}

// ======================= waveform kernel (R15/R16 version, verbatim) ====================
constexpr int WV_NSL = 24;
constexpr float CNORM = 0.3989422804f;

constexpr int EST_S = 264;
constexpr int RS2_S = 72;
constexpr int WOFF_EST = 0;
constexpr int WOFF_RS2 = WOFF_EST + 32 * EST_S * 2;
constexpr int WV_SMEM  = WOFF_RS2 + 256 * RS2_S * 2;

__global__ __launch_bounds__(256, 2)
void waveform_gemm(float* __restrict__ out) {
    extern __shared__ unsigned char sm[];
    u16*    EST  = reinterpret_cast<u16*>(sm + WOFF_EST);
    uint32* RS2w = reinterpret_cast<uint32*>(sm + WOFF_RS2);

    const int tid  = threadIdx.x;
    const int lane = tid & 31;
    const int wid  = tid >> 5;
    const int g    = lane >> 2, tg = lane & 3;
    const int tile = blockIdx.x;
    const int t0   = tile * 32;

    const int cnt = min(g_binCnt[tile], BCAP);
    const int nc  = (cnt + 255) >> 8;
    const int emax = cnt - 1;

    float C[8];
    #pragma unroll
    for (int i = 0; i < 8; i++) C[i] = 0.f;

    const int mt = wid & 3;
    const int nh = wid >> 2;

    const int arow = (lane & 7) + ((lane >> 4) << 3);
    const int acol = mt * 16 + ((lane >> 3) & 1) * 8;
    const uint32 lmA = smem_u32(sm + WOFF_RS2) + (uint32)((arow * RS2_S + acol) * 2);
    const int rowB = (lane & 7) + ((lane >> 4) << 3);
    const uint32 lmB = smem_u32(sm + WOFF_EST) +
        (uint32)(((nh * 16 + rowB) * EST_S + (((lane >> 3) & 1) * 8)) * 2);

    for (int c = blockIdx.y; c < nc; c += WV_NSL) {
        const int cb = c << 8;
        const int cend = min(cb + 256, cnt);

        {
            const int e = cb + tid;
            const float zz = g_binZ[tile * BCAP + min(e, emax)];
            const float cn = (e < cend) ? CNORM : 0.f;
            const float d0 = (float)t0 - zz;
            #pragma unroll
            for (int j = 0; j < 32; j++) {
                float d = d0 + (float)j;
                float ex = __expf(-0.5f * d * d);
                EST[j * EST_S + tid] = __bfloat16_as_ushort(__float2bfloat16_rn(cn * ex));
            }
        }
        {
            const uint32* src = g_Rbin + ((size_t)tile * BCAP + cb + wid * 32) * 32;
            const int lrow_in = (lane >> 3);
            const int word = (lane & 7) * 4;
            #pragma unroll
            for (int q = 0; q < 8; q++) {
                const int lrow = q * 4 + lrow_in;
                uint4 v = *reinterpret_cast<const uint4*>(src + lrow * 32 + word);
                *reinterpret_cast<uint4*>(&RS2w[(wid * 32 + lrow) * (RS2_S / 2) + word]) = v;
            }
        }
        __syncthreads();

        #pragma unroll
        for (int ks = 0; ks < 16; ks++) {
            uint32 a0, a1, a2, a3, b0, b1, b2, b3;
            ldsm4t(a0, a1, a2, a3, lmA + (uint32)(ks * 16 * RS2_S * 2));
            ldsm4 (b0, b1, b2, b3, lmB + (uint32)(ks * 32));
            mma16816(&C[0], a0, a1, a2, a3, b0, b1);
            mma16816(&C[4], a0, a1, a2, a3, b2, b3);
        }
        __syncthreads();
    }

    #pragma unroll
    for (int nt = 0; nt < 2; nt++) {
        const int tcol = t0 + (nh * 2 + nt) * 8 + 2 * tg;
        const int srow = mt * 16 + g;
        atomicAdd(&out[srow * 1024 + tcol],           C[nt * 4 + 0]);
        atomicAdd(&out[srow * 1024 + tcol + 1],       C[nt * 4 + 1]);
        atomicAdd(&out[(srow + 8) * 1024 + tcol],     C[nt * 4 + 2]);
        atomicAdd(&out[(srow + 8) * 1024 + tcol + 1], C[nt * 4 + 3]);
    }

    if (tid == 0) {
        int d = atomicAdd(&g_done[tile], 1);
        if (d == WV_NSL - 1) { g_binCnt[tile] = 0; g_done[tile] = 0; }
    }
}

// ---------------- launch ----------------
extern "C" void kernel_launch(void* const* d_in, const int* in_sizes, int n_in,
                              void* d_out, int out_size) {
    const float*  photons = (const float*)d_in[0];
    const float2* xy      = (const float2*)d_in[1];
    const float*  zpos    = (const float*)d_in[2];
    const float*  W1      = (const float*)d_in[3];
    const float*  b1      = (const float*)d_in[4];
    const float*  W2      = (const float*)d_in[5];
    const float*  b2      = (const float*)d_in[6];
    const float*  W3      = (const float*)d_in[7];
    const float*  b3      = (const float*)d_in[8];
    float* out = (float*)d_out;

    cudaFuncSetAttribute(mlp_kernel, cudaFuncAttributeMaxDynamicSharedMemorySize, MLP_SMEM);
    cudaFuncSetAttribute(waveform_gemm, cudaFuncAttributeMaxDynamicSharedMemorySize, WV_SMEM);

    mlp_kernel<<<MLP_GRID, 256, MLP_SMEM>>>(zpos, (float4*)out, photons, xy,
                                            W1, b1, W2, b2, W3, b3);

    dim3 wgrid(TICKS / 32, WV_NSL);
    waveform_gemm<<<wgrid, 256, WV_SMEM>>>(out);
}